// round 12
// baseline (speedup 1.0000x reference)
#include <cuda_runtime.h>
#include <cuda_fp16.h>
#include <cstdint>

#define CC   3
#define OO   8
#define HH   128
#define WW   128
#define HO   124
#define WO   124
#define P25  25
#define CHSTRIDE (CC * HO * WO)

#define XT_W  36                  // 32 + 4 halo
#define XT_H  22                  // 18 + 4 halo

// One row, TWO o-channels sharing the same window ring.
// w[p] = (x, -x) half2; ka/kb[p] = (-K_hit, +K_miss) half2 for o and o+4.
// min over both halves of (w + k) yields (hit, -miss); out = lo + hi.
template<int J>
__device__ __forceinline__ float2 row_compute2(const __half2* __restrict__ w,
                                               const __half2* __restrict__ ka,
                                               const __half2* __restrict__ kb)
{
    __half2 ca[5], cb[5];
#pragma unroll
    for (int u = 0; u < 5; ++u) {
        const int s = ((J + u) % 5) * 5;
        __half2 a = __hadd2(w[s], ka[u * 5]);
        __half2 b = __hadd2(w[s], kb[u * 5]);
#pragma unroll
        for (int v = 1; v < 5; ++v) {
            a = __hmin2(a, __hadd2(w[s + v], ka[u * 5 + v]));
            b = __hmin2(b, __hadd2(w[s + v], kb[u * 5 + v]));
        }
        ca[u] = a; cb[u] = b;
    }
    const __half2 ra = __hmin2(__hmin2(__hmin2(ca[0], ca[1]),
                                       __hmin2(ca[2], ca[3])), ca[4]);
    const __half2 rb = __hmin2(__hmin2(__hmin2(cb[0], cb[1]),
                                       __hmin2(cb[2], cb[3])), cb[4]);
    return make_float2(__low2float(ra) + __high2float(ra),
                       __low2float(rb) + __high2float(rb));
}

// Load x row into ring slot (J+4)%5, compute BOTH o outputs for row rbase+J.
#define ROW_STEP(J)                                                              \
    do {                                                                         \
        const __half2* nr = sxr + ((J) + 4) * XT_W;                              \
        _Pragma("unroll")                                                        \
        for (int v = 0; v < 5; ++v)                                              \
            w[(((J) + 4) % 5) * 5 + v] = nr[v];                                  \
        const float2 r = row_compute2<(J)>(w, ka, kb);                           \
        opA[0] = r.x;                                                            \
        opB[0] = r.y;                                                            \
        opA += WO; opB += WO;                                                    \
    } while (0)

__global__ __launch_bounds__(128, 5)
void mnn_kernel(const float* __restrict__ x,
                const float* __restrict__ kh_g,
                const float* __restrict__ km_g,
                float* __restrict__ out)
{
    __shared__ __half2 sxh[XT_H * XT_W];   // (x, -x) tile: 22 x 36
    __shared__ __half2 wsm[OO * P25];      // (-kh, +km) for all 8 o, this c

    const int tx  = threadIdx.x;           // 0..31 column
    const int ty  = threadIdx.y;           // 0..3  -> o = ty and ty+4
    const int tid = ty * 32 + tx;

    // Overlapping tiles both axes -> all store lanes in-range; overlap cells
    // rewritten with identical values (deterministic). Even column origins
    // keep the float2 staging loads 8-byte aligned.
    static const int WO0[4] = {0, 30, 62, 92};
    static const int HO0[7] = {0, 18, 36, 54, 72, 90, 106};
    const int wo0 = WO0[blockIdx.x];
    const int ho0 = HO0[blockIdx.y];
    const int bc  = blockIdx.z;             // b*CC + c
    const int b   = bc / CC;
    const int c   = bc % CC;

    // ---- cooperative weight staging (<=2 LDG pairs per thread) ----
    for (int i = tid; i < OO * P25; i += 128) {
        const int oo = i / P25;
        const int p  = i % P25;
        const float kh = __ldg(kh_g + (oo * CC + c) * P25 + p);
        const float km = __ldg(km_g + (oo * CC + c) * P25 + p);
        wsm[i] = __halves2half2(__float2half_rn(-kh), __float2half_rn(km));
    }

    // ---- x tile staged via float2, as (x, -x) half2 ----
    const float* __restrict__ xb = x + (size_t)bc * HH * WW;
    for (int i = tid; i < (XT_H * XT_W) / 2; i += 128) {   // 396 float2
        const int e   = 2 * i;
        const int rr  = e / XT_W;
        const int cc2 = e % XT_W;                          // even
        const float2 v2 = *(const float2*)(xb + (ho0 + rr) * WW + wo0 + cc2);
        const __half h0 = __float2half_rn(v2.x);
        const __half h1 = __float2half_rn(v2.y);
        sxh[e]     = __halves2half2(h0, __hneg(h0));
        sxh[e + 1] = __halves2half2(h1, __hneg(h1));
    }
    __syncthreads();

    // ---- this thread's two weight sets from smem (broadcast LDS) ----
    __half2 ka[P25], kb[P25];
    {
        const __half2* __restrict__ wa = &wsm[ty * P25];
        const __half2* __restrict__ wb = &wsm[(ty + 4) * P25];
#pragma unroll
        for (int p = 0; p < P25; ++p) { ka[p] = wa[p]; kb[p] = wb[p]; }
    }

    // ---- ring prologue: x rows 0..3 into slots 0..3 ----
    __half2 w[P25];
#pragma unroll
    for (int i = 0; i < 4; ++i)
#pragma unroll
        for (int v = 0; v < 5; ++v)
            w[i * 5 + v] = sxh[i * XT_W + tx + v];

    float* __restrict__ opA =
        out + ((size_t)(b * OO * CC + ty * CC + c) * HO + ho0) * WO + wo0 + tx;
    float* __restrict__ opB = opA + 4 * CHSTRIDE;

    const __half2* sxr = sxh + tx;          // advances 5 rows per chunk

    // ---- 3 chunks x 5 rows + 3 tail = 18 output rows ----
#pragma unroll 1
    for (int rc = 0; rc < 3; ++rc) {
        ROW_STEP(0);
        ROW_STEP(1);
        ROW_STEP(2);
        ROW_STEP(3);
        ROW_STEP(4);
        sxr += 5 * XT_W;
    }
    ROW_STEP(0);   // row 15
    ROW_STEP(1);   // row 16
    ROW_STEP(2);   // row 17
}

extern "C" void kernel_launch(void* const* d_in, const int* in_sizes, int n_in,
                              void* d_out, int out_size)
{
    const float* x     = (const float*)d_in[0];
    const float* K_hit = (const float*)d_in[1];
    const float* K_mis = (const float*)d_in[2];
    float* out = (float*)d_out;

    dim3 grid(4, 7, OO * CC);     // 672 blocks, cap 5/SM -> single wave
    dim3 block(32, 4);
    mnn_kernel<<<grid, block>>>(x, K_hit, K_mis, out);
}

// round 13
// speedup vs baseline: 1.1278x; 1.1278x over previous
#include <cuda_runtime.h>
#include <cuda_fp16.h>
#include <cstdint>

#define CC   3
#define OO   8
#define HH   128
#define WW   128
#define HO   124
#define WO   124
#define P25  25

#define ROWSPAN 21                // 6 overlapping row-tiles: 0,21,42,63,84,103
#define XT_W  36                  // 32 + 4 halo
#define XT_H  25                  // 21 + 4 halo

// One output row from the 5-slot ring (slot = xrow % 5), phase J = row % 5.
// w[p] = (x, -x) half2; kp[p] = (-K_hit, +K_miss) half2.
// min over both halves of (w + kp) yields (hit, -miss).
template<int J>
__device__ __forceinline__ float row_compute(const __half2* __restrict__ w,
                                             const __half2* __restrict__ kp)
{
    __half2 cu[5];
#pragma unroll
    for (int u = 0; u < 5; ++u) {
        const int s = ((J + u) % 5) * 5;
        __half2 acc = __hadd2(w[s], kp[u * 5]);
#pragma unroll
        for (int v = 1; v < 5; ++v)
            acc = __hmin2(acc, __hadd2(w[s + v], kp[u * 5 + v]));
        cu[u] = acc;
    }
    const __half2 r = __hmin2(__hmin2(__hmin2(cu[0], cu[1]),
                                      __hmin2(cu[2], cu[3])), cu[4]);
    return __low2float(r) + __high2float(r);   // hit - miss
}

// Step J of a 5-row chunk: load x row (rbase+J+4) into ring slot (J+4)%5,
// compute output row rbase+J, store at static offset J*WO.
#define ROW_STEP(J)                                                              \
    do {                                                                         \
        const __half2* nr = sxr + ((J) + 4) * XT_W;                              \
        _Pragma("unroll")                                                        \
        for (int v = 0; v < 5; ++v)                                              \
            w[(((J) + 4) % 5) * 5 + v] = nr[v];                                  \
        op[(J) * WO] = row_compute<(J)>(w, kp);                                  \
    } while (0)

__global__ __launch_bounds__(256, 4)
void mnn_kernel(const float* __restrict__ x,
                const float* __restrict__ kh_g,
                const float* __restrict__ km_g,
                float* __restrict__ out)
{
    __shared__ __half2 sxh[XT_H * XT_W];   // (x, -x) tile: 25 x 36
    __shared__ __half2 wsm[OO * P25];      // (-kh, +km) for all 8 o, this c

    const int tx  = threadIdx.x;           // 0..31 column
    const int o   = threadIdx.y;           // 0..7  output channel
    const int tid = o * 32 + tx;

    // Overlapping tiles both axes -> all store lanes in-range; overlap cells
    // rewritten with identical values (deterministic). Even column origins
    // keep the float2 staging loads 8-byte aligned.
    static const int WO0[4] = {0, 30, 62, 92};
    const int wo0 = WO0[blockIdx.x];
    const int ho0 = (blockIdx.y == 5) ? 103 : blockIdx.y * ROWSPAN;
    const int bc  = blockIdx.z;             // b*CC + c
    const int b   = bc / CC;
    const int c   = bc % CC;

    // ---- cooperative weight staging: 1 LDG pair per thread (tid < 200) ----
    if (tid < OO * P25) {
        const int oo = tid / P25;
        const int p  = tid % P25;
        const float kh = __ldg(kh_g + (oo * CC + c) * P25 + p);
        const float km = __ldg(km_g + (oo * CC + c) * P25 + p);
        wsm[tid] = __halves2half2(__float2half_rn(-kh), __float2half_rn(km));
    }

    // ---- x tile staged via float2 (2 LDG.64/thread), packed (x, -x) ----
    const float* __restrict__ xb = x + (size_t)bc * HH * WW;
    for (int i = tid; i < (XT_H * XT_W) / 2; i += 256) {     // 450 pairs
        const int e   = 2 * i;
        const int rr  = e / XT_W;
        const int cc2 = e % XT_W;                            // even
        const float2 v2 = *(const float2*)(xb + (ho0 + rr) * WW + wo0 + cc2);
        const __half h0 = __float2half_rn(v2.x);
        const __half h1 = __float2half_rn(v2.y);
        sxh[e]     = __halves2half2(h0, __hneg(h0));
        sxh[e + 1] = __halves2half2(h1, __hneg(h1));
    }
    __syncthreads();

    // ---- per-thread weights from smem (warp-uniform broadcast LDS) ----
    __half2 kp[P25];
    {
        const __half2* __restrict__ wp = &wsm[o * P25];
#pragma unroll
        for (int p = 0; p < P25; ++p) kp[p] = wp[p];
    }

    // ---- ring prologue: x rows 0..3 into slots 0..3 ----
    __half2 w[P25];
#pragma unroll
    for (int i = 0; i < 4; ++i)
#pragma unroll
        for (int v = 0; v < 5; ++v)
            w[i * 5 + v] = sxh[i * XT_W + tx + v];

    float* __restrict__ op =
        out + ((size_t)(b * OO * CC + o * CC + c) * HO + ho0) * WO + wo0 + tx;

    const __half2* sxr = sxh + tx;          // advances 5 rows per chunk

    // ---- 4 chunks x 5 rows + 1 tail = 21 output rows ----
#pragma unroll 1
    for (int rc = 0; rc < 4; ++rc) {
        ROW_STEP(0);
        ROW_STEP(1);
        ROW_STEP(2);
        ROW_STEP(3);
        ROW_STEP(4);
        sxr += 5 * XT_W;
        op  += 5 * WO;
    }
    ROW_STEP(0);   // row 20
}

extern "C" void kernel_launch(void* const* d_in, const int* in_sizes, int n_in,
                              void* d_out, int out_size)
{
    const float* x     = (const float*)d_in[0];
    const float* K_hit = (const float*)d_in[1];
    const float* K_mis = (const float*)d_in[2];
    float* out = (float*)d_out;

    dim3 grid(4, 6, OO * CC);     // 576 blocks, cap 4/SM -> balanced single wave
    dim3 block(32, 8);
    mnn_kernel<<<grid, block>>>(x, K_hit, K_mis, out);
}